// round 6
// baseline (speedup 1.0000x reference)
#include <cuda_runtime.h>
#include <cuda_bf16.h>

// Problem constants (fixed by setup_inputs)
#define BSZ   4
#define CCH   256
#define HWSZ  1024      // 32*32
#define NQ    300
#define NCLS  80
#define TOPK  150
#define NQ4   (HWSZ * BSZ * CCH / 4)   // 262144 float4 per output array
#define ZBLK  256                       // zero-fill blocks (1024 thr each)
// batched_h = batched_w = 512, grid step = 16

__device__ int d_src[BSZ][HWSZ];
__device__ int d_objnum[BSZ];

// monotone float->uint map: preserves >, ==, < for all non-NaN floats
__device__ __forceinline__ unsigned fmap(float f) {
    unsigned u = __float_as_uint(f);
    return (u & 0x80000000u) ? ~u : (u | 0x80000000u);
}

// ---------------------------------------------------------------------------
// Kernel A: blocks 0..3 = per-batch prep; blocks 4..259 = zero-fill of the
// whole output. The two groups are independent and coschedule, so the node
// costs max(prep, zerofill), not the sum.
// out layout: [sparse_key (1024,4,256)][sparse_key_pos (1024,4,256)] fp32
// ---------------------------------------------------------------------------
__global__ void __launch_bounds__(1024, 1)
prep_zero_kernel(const float* __restrict__ coord,       // (BSZ,NQ,4)
                 const float* __restrict__ cls_logits,  // (BSZ,NQ,NCLS)
                 const int*   __restrict__ sizes,       // (BSZ,2)
                 const unsigned char* __restrict__ padmask, // (BSZ,HWSZ)
                 float* __restrict__ out)
{
    const int bid = blockIdx.x;
    const int tid = threadIdx.x;

    if (bid >= BSZ) {
        // ---------------- zero-fill: 2 x STG.128 per thread ---------------
        const int q = (bid - BSZ) * 1024 + tid;      // 0..262143
        const float4 z = make_float4(0.f, 0.f, 0.f, 0.f);
        ((float4*)out)[q]       = z;
        ((float4*)out)[NQ4 + q] = z;
        return;
    }

    // ======================= PREP (batch b = bid) =========================
    __shared__ __align__(16) unsigned smax[NQ];   // mapped max bits
    __shared__ int      srank[NQ];
    __shared__ unsigned rowmask[32];
    __shared__ int      wsum[32];

    const int b    = bid;
    const int lane = tid & 31;
    const int wid  = tid >> 5;

    if (tid < NQ)  { smax[tid] = 0u; srank[tid] = 0; }
    if (tid < 32)  rowmask[tid] = 0u;
    __syncthreads();

    const int  row  = tid / 3;          // 0..341
    const int  part = tid - row * 3;    // 0..2
    const bool act  = (tid < 3 * NQ);   // 900 active

    // --- 1) class max: 3 threads/row, 7 batched float4 loads each ---------
    if (act) {
        const float4* r = (const float4*)(cls_logits + (size_t)(b * NQ + row) * NCLS);
        const int k0 = part * 7;        // chunks 0..6, 7..13, 14..19
        float m = -1e30f;
        #pragma unroll
        for (int kk = 0; kk < 7; kk++) {
            const int k = k0 + kk;
            if (k < NCLS / 4) {
                float4 v = r[k];
                m = fmaxf(m, fmaxf(fmaxf(v.x, v.y), fmaxf(v.z, v.w)));
            }
        }
        atomicMax(&smax[row], fmap(m));
    }
    __syncthreads();

    // --- 2) rank: 3 x 100 comparisons/row, uint4 smem reads ---------------
    if (act) {
        const unsigned vi = smax[row];
        const int j0 = part * 100;      // byte offset 0/400/800: 16B aligned
        int cnt = 0;
        const uint4* sv4 = (const uint4*)(smax + j0);
        #pragma unroll 5
        for (int jj = 0; jj < 25; jj++) {
            const uint4 v = sv4[jj];
            const int j = j0 + jj * 4;
            cnt += (v.x > vi) || (v.x == vi && (j + 0) < row);
            cnt += (v.y > vi) || (v.y == vi && (j + 1) < row);
            cnt += (v.z > vi) || (v.z == vi && (j + 2) < row);
            cnt += (v.w > vi) || (v.w == vi && (j + 3) < row);
        }
        atomicAdd(&srank[row], cnt);
    }
    __syncthreads();

    // --- 3) top-150 rows -> scaled boxes -> raster into rowmask ------------
    const float ts0 = (float)sizes[b * 2 + 0];
    const float ts1 = (float)sizes[b * 2 + 1];
    if (tid < NQ && srank[tid] < TOPK) {
        const float* bx = coord + (size_t)(b * NQ + tid) * 4;
        float cx = bx[0], cy = bx[1], bw = bx[2], bh = bx[3];
        // one rounding per op (matches XLA); *0.0625f is exact (exp shift)
        float x1 = ts0 * (cx - 0.5f * bw);
        float y1 = ts1 * (cy - 0.5f * bh);
        float x2 = ts0 * (cx + 0.5f * bw);
        float y2 = ts1 * (cy + 0.5f * bh);
        // j*16 > x1 <=> j > x1/16 (exact);  j*16 < x2 <=> j < x2/16
        int jlo = (int)floorf(x1 * 0.0625f) + 1;
        int jhi = (int)ceilf (x2 * 0.0625f) - 1;
        int ilo = (int)floorf(y1 * 0.0625f) + 1;
        int ihi = (int)ceilf (y2 * 0.0625f) - 1;
        jlo = max(jlo, 0);  jhi = min(jhi, 31);
        ilo = max(ilo, 0);  ihi = min(ihi, 31);
        if (jlo <= jhi && ilo <= ihi) {
            unsigned jmask = ((jhi == 31) ? 0xFFFFFFFFu : ((1u << (jhi + 1)) - 1u))
                           & ~((1u << jlo) - 1u);
            for (int i = ilo; i <= ihi; i++) atomicOr(&rowmask[i], jmask);
        }
    }
    __syncthreads();

    // --- 4) per-point mask + ballot compaction (ascending index order) ----
    const int gi = tid >> 5, gj = tid & 31;
    const int inbox = (rowmask[gi] >> gj) & 1u;
    const int om = (!inbox) | (padmask[b * HWSZ + tid] != 0);

    unsigned bal = __ballot_sync(0xffffffffu, om);
    if (lane == 0) wsum[wid] = __popc(bal);
    __syncthreads();
    if (wid == 0) {
        int v = wsum[lane];
        #pragma unroll
        for (int o = 1; o < 32; o <<= 1) {
            int tshf = __shfl_up_sync(0xffffffffu, v, o);
            if (lane >= o) v += tshf;
        }
        wsum[lane] = v;   // inclusive
    }
    __syncthreads();
    const int warp_off = wid ? wsum[wid - 1] : 0;
    const int pre = __popc(bal & ((1u << lane) - 1u));
    if (om) d_src[b][warp_off + pre] = tid;
    if (tid == 1023) d_objnum[b] = wsum[31];
}

// ---------------------------------------------------------------------------
// Kernel B: overwrite data rows only. Block = one (p,b) row; early exit when
// p >= objnum[b] (the common case). 64 threads cover 256 channels as float4.
// ---------------------------------------------------------------------------
__global__ void __launch_bounds__(64, 16)
gather_rows_kernel(const float* __restrict__ x,
                   const float* __restrict__ pos,
                   float* __restrict__ out)
{
    const int blk = blockIdx.x;          // p*4 + b
    const int b   = blk & 3;
    const int p   = blk >> 2;
    if (p >= d_objnum[b]) return;

    const int s = d_src[b][p];
    const int t = threadIdx.x;           // 0..63 -> channels t*4..t*4+3
    const size_t base = ((size_t)(b * CCH + t * 4) << 10) + s;

    float4 k4, p4;
    k4.x = __ldg(x + base);
    k4.y = __ldg(x + base + 1024);
    k4.z = __ldg(x + base + 2048);
    k4.w = __ldg(x + base + 3072);
    p4.x = __ldg(pos + base);
    p4.y = __ldg(pos + base + 1024);
    p4.z = __ldg(pos + base + 2048);
    p4.w = __ldg(pos + base + 3072);

    const size_t o = (size_t)blk * CCH + (size_t)t * 4;
    *(float4*)(out + o)                            = k4;
    *(float4*)(out + (size_t)NQ4 * 4 + o)          = p4;
}

// ---------------------------------------------------------------------------
extern "C" void kernel_launch(void* const* d_in, const int* in_sizes, int n_in,
                              void* d_out, int out_size)
{
    const float* x        = (const float*)d_in[0];  // (4,256,32,32)
    const float* pos      = (const float*)d_in[1];  // (4,256,32,32)
    const unsigned char* msk = (const unsigned char*)d_in[2]; // (4,32,32)
    const float* coord    = (const float*)d_in[3];  // (4,300,4)
    const float* clsl     = (const float*)d_in[4];  // (4,300,80)
    const int*   sizes    = (const int*)d_in[5];    // (4,2)
    float* out = (float*)d_out;

    prep_zero_kernel<<<BSZ + ZBLK, 1024>>>(coord, clsl, sizes, msk, out);
    gather_rows_kernel<<<BSZ * HWSZ, 64>>>(x, pos, out);
}

// round 7
// speedup vs baseline: 1.4076x; 1.4076x over previous
#include <cuda_runtime.h>
#include <cuda_bf16.h>

// Problem constants (fixed by setup_inputs)
#define BSZ   4
#define CCH   256
#define HWSZ  1024      // 32*32
#define NQ    300
#define NCLS  80
#define TOPK  150
#define NQ4   (HWSZ * BSZ * CCH / 4)   // 262144 float4 per output array
// batched_h = batched_w = 512, grid step = 16

__device__ int d_src[BSZ][HWSZ];
__device__ int d_objnum[BSZ];

// monotone float->uint map: preserves >, ==, < for all non-NaN floats
__device__ __forceinline__ unsigned fmap(float f) {
    unsigned u = __float_as_uint(f);
    return (u & 0x80000000u) ? ~u : (u | 0x80000000u);
}

// ---------------------------------------------------------------------------
// Kernel 1: control.  <<<4, 1024>>>
// class-max (3 thr/row, batched loads) -> rank (uint4 smem) -> box append ->
// ATOMIC-FREE raster: warp w owns grid row w, lanes OR 5 boxes each,
// shfl-OR reduce -> rowmask[w].  Then ballot compaction.
// ---------------------------------------------------------------------------
__global__ void __launch_bounds__(1024, 1)
prep_kernel(const float* __restrict__ coord,       // (BSZ,NQ,4)
            const float* __restrict__ cls_logits,  // (BSZ,NQ,NCLS)
            const int*   __restrict__ sizes,       // (BSZ,2)
            const unsigned char* __restrict__ padmask) // (BSZ,HWSZ)
{
    __shared__ __align__(16) unsigned smax[NQ];   // mapped max bits
    __shared__ int      srank[NQ];
    __shared__ unsigned bjmask[TOPK + 10];        // per selected box: col mask
    __shared__ int      birange[TOPK + 10];       // ilo | (ihi<<8)
    __shared__ unsigned rowmask[32];
    __shared__ int      wsum[32];
    __shared__ int      nsel;

    const int b    = blockIdx.x;
    const int tid  = threadIdx.x;
    const int lane = tid & 31;
    const int wid  = tid >> 5;

    if (tid < NQ)  { smax[tid] = 0u; srank[tid] = 0; }
    if (tid == 0)  nsel = 0;
    __syncthreads();

    const int  row  = tid / 3;          // 0..341
    const int  part = tid - row * 3;    // 0..2
    const bool act  = (tid < 3 * NQ);   // 900 active

    // --- 1) class max: 3 threads/row, 7 batched float4 loads each ---------
    if (act) {
        const float4* r = (const float4*)(cls_logits + (size_t)(b * NQ + row) * NCLS);
        const int k0 = part * 7;        // chunks 0..6, 7..13, 14..19
        float m = -1e30f;
        #pragma unroll
        for (int kk = 0; kk < 7; kk++) {
            const int k = k0 + kk;
            if (k < NCLS / 4) {
                float4 v = r[k];
                m = fmaxf(m, fmaxf(fmaxf(v.x, v.y), fmaxf(v.z, v.w)));
            }
        }
        atomicMax(&smax[row], fmap(m));
    }
    __syncthreads();

    // --- 2) rank: 3 x 100 comparisons/row, uint4 smem reads ---------------
    if (act) {
        const unsigned vi = smax[row];
        const int j0 = part * 100;      // 16B aligned (400B offsets)
        int cnt = 0;
        const uint4* sv4 = (const uint4*)(smax + j0);
        #pragma unroll 5
        for (int jj = 0; jj < 25; jj++) {
            const uint4 v = sv4[jj];
            const int j = j0 + jj * 4;
            cnt += (v.x > vi) || (v.x == vi && (j + 0) < row);
            cnt += (v.y > vi) || (v.y == vi && (j + 1) < row);
            cnt += (v.z > vi) || (v.z == vi && (j + 2) < row);
            cnt += (v.w > vi) || (v.w == vi && (j + 3) < row);
        }
        atomicAdd(&srank[row], cnt);
    }
    __syncthreads();

    // --- 3) top-150 rows -> scaled boxes -> append (ilo,ihi,jmask) --------
    const float ts0 = (float)sizes[b * 2 + 0];
    const float ts1 = (float)sizes[b * 2 + 1];
    if (tid < NQ && srank[tid] < TOPK) {
        const float* bx = coord + (size_t)(b * NQ + tid) * 4;
        float cx = bx[0], cy = bx[1], bw = bx[2], bh = bx[3];
        // one rounding per op (matches XLA); *0.0625f is exact (exp shift)
        float x1 = ts0 * (cx - 0.5f * bw);
        float y1 = ts1 * (cy - 0.5f * bh);
        float x2 = ts0 * (cx + 0.5f * bw);
        float y2 = ts1 * (cy + 0.5f * bh);
        // j*16 > x1 <=> j > x1/16 (exact);  j*16 < x2 <=> j < x2/16
        int jlo = (int)floorf(x1 * 0.0625f) + 1;
        int jhi = (int)ceilf (x2 * 0.0625f) - 1;
        int ilo = (int)floorf(y1 * 0.0625f) + 1;
        int ihi = (int)ceilf (y2 * 0.0625f) - 1;
        jlo = max(jlo, 0);  jhi = min(jhi, 31);
        ilo = max(ilo, 0);  ihi = min(ihi, 31);
        if (jlo <= jhi && ilo <= ihi) {
            unsigned jmask = ((jhi == 31) ? 0xFFFFFFFFu : ((1u << (jhi + 1)) - 1u))
                           & ~((1u << jlo) - 1u);
            int pos = atomicAdd(&nsel, 1);   // set semantics: order irrelevant
            bjmask[pos]  = jmask;
            birange[pos] = ilo | (ihi << 8);
        }
    }
    __syncthreads();

    // --- 4) atomic-free raster: warp wid owns grid row i=wid ---------------
    {
        const int nb = nsel;
        unsigned m = 0;
        #pragma unroll
        for (int u = 0; u < 5; u++) {           // 32 lanes x 5 >= 150
            const int idx = lane * 5 + u;
            if (idx < nb) {
                const int r   = birange[idx];
                const int ilo = r & 255, ihi = r >> 8;
                if (wid >= ilo && wid <= ihi) m |= bjmask[idx];
            }
        }
        #pragma unroll
        for (int off = 16; off > 0; off >>= 1)
            m |= __shfl_xor_sync(0xffffffffu, m, off);
        if (lane == 0) rowmask[wid] = m;
    }
    __syncthreads();

    // --- 5) per-point mask + ballot compaction (ascending index order) ----
    const int gi = tid >> 5, gj = tid & 31;
    const int inbox = (rowmask[gi] >> gj) & 1u;
    const int om = (!inbox) | (padmask[b * HWSZ + tid] != 0);

    unsigned bal = __ballot_sync(0xffffffffu, om);
    if (lane == 0) wsum[wid] = __popc(bal);
    __syncthreads();
    if (wid == 0) {
        int v = wsum[lane];
        #pragma unroll
        for (int o = 1; o < 32; o <<= 1) {
            int tshf = __shfl_up_sync(0xffffffffu, v, o);
            if (lane >= o) v += tshf;
        }
        wsum[lane] = v;   // inclusive
    }
    __syncthreads();
    const int warp_off = wid ? wsum[wid - 1] : 0;
    const int pre = __popc(bal & ((1u << lane) - 1u));
    if (om) d_src[b][warp_off + pre] = tid;
    if (tid == 1023) d_objnum[b] = wsum[31];
}

// ---------------------------------------------------------------------------
// Kernel 2: tiled gather+transpose (lanes along gathered s for reads).
// 32p x 32c tiles; grid 4*32*8=1024 blocks, 256 threads.
// Read: 8 batched LDG -> regs -> STS (conflict-free, stride 33).
// Write: conflict-free LDS -> 2x STG.128 per thread (fully coalesced).
// out: [sparse_key (1024,4,256)][sparse_key_pos (1024,4,256)] fp32
// ---------------------------------------------------------------------------
#define TS 33

__global__ void __launch_bounds__(256, 4)
gather_kernel(const float* __restrict__ x,
              const float* __restrict__ pos,
              float* __restrict__ out)
{
    const int blk = blockIdx.x;
    const int b   = blk & (BSZ - 1);
    const int pt  = (blk >> 2) & 31;     // 0..31
    const int ct  = blk >> 7;            // 0..7
    const int p0  = pt * 32;
    const int c0  = ct * 32;
    const int tid = threadIdx.x;

    const int objnum = d_objnum[b];
    const size_t out2 = (size_t)NQ4 * 4;

    const int cl4 = tid & 7;             // float4 slot (channels cl4*4..+3)
    const int pl  = tid >> 3;            // 0..31
    const size_t o = (size_t)(p0 + pl) * (BSZ * CCH) + b * CCH + c0 + cl4 * 4;

    if (p0 >= objnum) {                  // rare fast path: pure zeros
        const float4 z = make_float4(0.f, 0.f, 0.f, 0.f);
        *(float4*)(out + o)        = z;
        *(float4*)(out + out2 + o) = z;
        return;
    }

    __shared__ float tk[32 * TS];
    __shared__ float tp[32 * TS];
    __shared__ int   ss[32];

    if (tid < 32) {
        const int p = p0 + tid;
        ss[tid] = (p < objnum) ? d_src[b][p] : -1;
    }
    __syncthreads();

    const int tx = tid & 31;             // p-lane (along gathered s)
    const int ty = tid >> 5;             // warp 0..7
    const int s  = ss[tx];

    // batched loads: 8 independent LDGs in flight before any STS
    float vk[4], vp[4];
    #pragma unroll
    for (int it = 0; it < 4; it++) {
        const int cl = it * 8 + ty;      // 0..31
        const size_t base = ((size_t)(b * CCH + c0 + cl) << 10);
        vk[it] = (s >= 0) ? __ldg(x + base + s)   : 0.f;
        vp[it] = (s >= 0) ? __ldg(pos + base + s) : 0.f;
    }
    #pragma unroll
    for (int it = 0; it < 4; it++) {
        const int cl = it * 8 + ty;
        tk[tx * TS + cl] = vk[it];
        tp[tx * TS + cl] = vp[it];
    }
    __syncthreads();

    // write: 4 scalar LDS (conflict-free) -> STG.128, per array
    float4 k4, p4;
    k4.x = tk[pl * TS + cl4 * 4 + 0];
    k4.y = tk[pl * TS + cl4 * 4 + 1];
    k4.z = tk[pl * TS + cl4 * 4 + 2];
    k4.w = tk[pl * TS + cl4 * 4 + 3];
    p4.x = tp[pl * TS + cl4 * 4 + 0];
    p4.y = tp[pl * TS + cl4 * 4 + 1];
    p4.z = tp[pl * TS + cl4 * 4 + 2];
    p4.w = tp[pl * TS + cl4 * 4 + 3];
    *(float4*)(out + o)        = k4;
    *(float4*)(out + out2 + o) = p4;
}

// ---------------------------------------------------------------------------
extern "C" void kernel_launch(void* const* d_in, const int* in_sizes, int n_in,
                              void* d_out, int out_size)
{
    const float* x        = (const float*)d_in[0];  // (4,256,32,32)
    const float* pos      = (const float*)d_in[1];  // (4,256,32,32)
    const unsigned char* msk = (const unsigned char*)d_in[2]; // (4,32,32)
    const float* coord    = (const float*)d_in[3];  // (4,300,4)
    const float* clsl     = (const float*)d_in[4];  // (4,300,80)
    const int*   sizes    = (const int*)d_in[5];    // (4,2)
    float* out = (float*)d_out;

    prep_kernel<<<BSZ, 1024>>>(coord, clsl, sizes, msk);
    gather_kernel<<<BSZ * 32 * 8, 256>>>(x, pos, out);
}